// round 5
// baseline (speedup 1.0000x reference)
#include <cuda_runtime.h>
#include <cuda_bf16.h>
#include <math.h>

// Problem constants
#define BATCH 4
#define SEQ   2048
#define NH    16
#define DH    64
#define DMODEL 1024
#define M_ROWS (BATCH * SEQ)          // 8192
#define QKV_N  (3 * DMODEL)           // 3072

// Scratch (device globals; allocations are forbidden)
__device__ float g_Q[BATCH * NH * SEQ * DH];    // [b,h,l,d]
__device__ float g_K[BATCH * NH * SEQ * DH];
__device__ float g_V[BATCH * NH * SEQ * DH];
__device__ float g_A[M_ROWS * DMODEL];          // attention output [b,l,h*64+d]
__device__ float g_cos[SEQ * (DH / 2)];
__device__ float g_sin[SEQ * (DH / 2)];

// ---------------------------------------------------------------------------
// RoPE table: cos/sin[l][i], i in [0,32). Double precision internally.
// ---------------------------------------------------------------------------
__global__ void rope_table_kernel() {
    int l = blockIdx.x;     // 0..2047
    int i = threadIdx.x;    // 0..31
    double inv = pow(10000.0, -(2.0 * (double)i) / (double)DH);
    double ph  = (double)l * inv;
    g_cos[l * 32 + i] = (float)cos(ph);
    g_sin[l * 32 + i] = (float)sin(ph);
}

// ---------------------------------------------------------------------------
// In-place RoPE on Q (which=0) or K (which=1). One thread per (even,odd) pair.
// Layout [bh][l][64] viewed as float2[ ... ][32].
// ---------------------------------------------------------------------------
__global__ void rope_apply_kernel(int which) {
    int p = blockIdx.x * blockDim.x + threadIdx.x;
    const int TOTAL = BATCH * NH * SEQ * 32;
    if (p >= TOTAL) return;
    float* T = which ? g_K : g_Q;
    float2* tp = (float2*)T;
    int i = p & 31;
    int l = (p >> 5) & (SEQ - 1);
    float2 v = tp[p];
    float c = g_cos[l * 32 + i];
    float s = g_sin[l * 32 + i];
    float2 r;
    r.x = v.x * c - v.y * s;
    r.y = v.x * s + v.y * c;
    tp[p] = r;
}

// ---------------------------------------------------------------------------
// Tiled SGEMM: C[M=8192, N] = A[M,K] @ B[K,N] + bias[N]
// mode 0: A = Aarg (x), epilogue scatters into g_Q/g_K/g_V [b,h,l,d]
// mode 1: A = g_A,      epilogue writes Cout row-major
// BM=128, BN=128, BK=8, 256 threads, 8x8 per-thread tile.
// ---------------------------------------------------------------------------
__global__ void __launch_bounds__(256)
sgemm_kernel(const float* __restrict__ Aarg, const float* __restrict__ B,
             const float* __restrict__ bias, float* __restrict__ Cout,
             int N, int K, int mode) {
    const int BM = 128, BN = 128, BK = 8;
    __shared__ float As[BK][BM];
    __shared__ float Bs[BK][BN];

    const float* A = (mode == 1) ? g_A : Aarg;

    int tid = threadIdx.x;
    int m0 = blockIdx.y * BM;
    int n0 = blockIdx.x * BN;

    int arow = tid >> 1;            // 0..127
    int acol = (tid & 1) * 4;       // 0 or 4
    int brow = tid >> 5;            // 0..7
    int bcol = (tid & 31) * 4;      // 0..124

    int ty = tid >> 4;              // 0..15
    int tx = tid & 15;              // 0..15

    float acc[8][8];
#pragma unroll
    for (int i = 0; i < 8; i++)
#pragma unroll
        for (int j = 0; j < 8; j++) acc[i][j] = 0.0f;

    const float* Aptr = A + (size_t)(m0 + arow) * K + acol;
    const float* Bptr = B + (size_t)brow * N + n0 + bcol;

    for (int k0 = 0; k0 < K; k0 += BK) {
        float4 av = *(const float4*)(Aptr + k0);
        float4 bv = *(const float4*)(Bptr + (size_t)k0 * N);
        As[acol + 0][arow] = av.x;
        As[acol + 1][arow] = av.y;
        As[acol + 2][arow] = av.z;
        As[acol + 3][arow] = av.w;
        *(float4*)&Bs[brow][bcol] = bv;
        __syncthreads();

#pragma unroll
        for (int k = 0; k < BK; k++) {
            float4 a0 = *(float4*)&As[k][ty * 8];
            float4 a1 = *(float4*)&As[k][ty * 8 + 4];
            float4 b0 = *(float4*)&Bs[k][tx * 8];
            float4 b1 = *(float4*)&Bs[k][tx * 8 + 4];
            float ar[8] = {a0.x, a0.y, a0.z, a0.w, a1.x, a1.y, a1.z, a1.w};
            float br[8] = {b0.x, b0.y, b0.z, b0.w, b1.x, b1.y, b1.z, b1.w};
#pragma unroll
            for (int i = 0; i < 8; i++)
#pragma unroll
                for (int j = 0; j < 8; j++)
                    acc[i][j] += ar[i] * br[j];
        }
        __syncthreads();
    }

    // Epilogue
#pragma unroll
    for (int i = 0; i < 8; i++) {
        int row = m0 + ty * 8 + i;
        int b = row >> 11;            // /2048
        int l = row & (SEQ - 1);
#pragma unroll
        for (int jc = 0; jc < 8; jc += 4) {
            int col = n0 + tx * 8 + jc;
            float4 bb = *(const float4*)(bias + col);
            float4 v;
            v.x = acc[i][jc + 0] + bb.x;
            v.y = acc[i][jc + 1] + bb.y;
            v.z = acc[i][jc + 2] + bb.z;
            v.w = acc[i][jc + 3] + bb.w;
            if (mode == 0) {
                int part = col >> 10;          // 0=q,1=k,2=v
                int rem  = col & 1023;
                int h    = rem >> 6;
                int d    = rem & 63;
                float* dst = (part == 0) ? g_Q : (part == 1) ? g_K : g_V;
                size_t off = ((size_t)((b * NH + h) * SEQ + l)) * DH + d;
                *(float4*)(dst + off) = v;
            } else {
                *(float4*)(Cout + (size_t)row * N + col) = v;
            }
        }
    }
}

// ---------------------------------------------------------------------------
// Flash attention (causal + key mask), fp32.
// Grid: (SEQ/128, BATCH*NH). 128 threads; thread t owns query row qbase+t.
// K/V tiles of 64 keys staged in SMEM; online softmax with lazy rescale.
// ---------------------------------------------------------------------------
__global__ void __launch_bounds__(128)
flash_attn_kernel(const int* __restrict__ mask) {
    __shared__ float Ks[64][64];
    __shared__ float Vs[64][64];
    __shared__ int   ms[64];

    int bh = blockIdx.y;
    int b  = bh >> 4;
    int h  = bh & 15;
    int qbase = blockIdx.x * 128;
    int t = threadIdx.x;
    int row = qbase + t;

    const float* qptr = g_Q + ((size_t)bh * SEQ + row) * DH;
    float4 q[16];
#pragma unroll
    for (int i = 0; i < 16; i++) q[i] = *(const float4*)(qptr + i * 4);

    float m = -INFINITY;
    float lsum = 0.0f;
    float4 o[16];
#pragma unroll
    for (int i = 0; i < 16; i++) o[i] = make_float4(0.f, 0.f, 0.f, 0.f);

    const float scale = 0.125f;  // 1/sqrt(64)
    int ntiles = blockIdx.x * 2 + 2;   // causal: keys up to qbase+127

    for (int tile = 0; tile < ntiles; tile++) {
        int kb = tile * 64;
        const float4* kp = (const float4*)(g_K + ((size_t)bh * SEQ + kb) * DH);
        const float4* vp = (const float4*)(g_V + ((size_t)bh * SEQ + kb) * DH);
#pragma unroll
        for (int i = 0; i < 8; i++) {
            ((float4*)Ks)[t + i * 128] = kp[t + i * 128];
            ((float4*)Vs)[t + i * 128] = vp[t + i * 128];
        }
        if (t < 64) ms[t] = mask[b * SEQ + kb + t];
        __syncthreads();

        int kmax = row - kb + 1;
        if (kmax > 64) kmax = 64;
        for (int kk = 0; kk < kmax; kk++) {
            if (!ms[kk]) continue;
            const float4* kr = (const float4*)&Ks[kk][0];
            float s0 = 0.f, s1 = 0.f, s2 = 0.f, s3 = 0.f;
#pragma unroll
            for (int i = 0; i < 16; i++) {
                float4 kv = kr[i];
                float4 qv = q[i];
                s0 += qv.x * kv.x;
                s1 += qv.y * kv.y;
                s2 += qv.z * kv.z;
                s3 += qv.w * kv.w;
            }
            float s = ((s0 + s1) + (s2 + s3)) * scale;
            if (s > m) {
                float c = __expf(m - s);   // 0 when m == -inf
                lsum *= c;
#pragma unroll
                for (int i = 0; i < 16; i++) {
                    o[i].x *= c; o[i].y *= c; o[i].z *= c; o[i].w *= c;
                }
                m = s;
            }
            float p = __expf(s - m);
            lsum += p;
            const float4* vr = (const float4*)&Vs[kk][0];
#pragma unroll
            for (int i = 0; i < 16; i++) {
                float4 vv = vr[i];
                o[i].x += p * vv.x;
                o[i].y += p * vv.y;
                o[i].z += p * vv.z;
                o[i].w += p * vv.w;
            }
        }
        __syncthreads();
    }

    float inv = (lsum > 0.f) ? (1.0f / lsum) : 0.f;
    float* op = g_A + ((size_t)(b * SEQ + row)) * DMODEL + h * DH;
#pragma unroll
    for (int i = 0; i < 16; i++) {
        float4 v;
        v.x = o[i].x * inv; v.y = o[i].y * inv;
        v.z = o[i].z * inv; v.w = o[i].w * inv;
        *(float4*)(op + i * 4) = v;
    }
}

// ---------------------------------------------------------------------------
// Launch
// ---------------------------------------------------------------------------
extern "C" void kernel_launch(void* const* d_in, const int* in_sizes, int n_in,
                              void* d_out, int out_size) {
    const float* x      = (const float*)d_in[0];
    const float* W_qkv  = (const float*)d_in[1];
    const float* b_qkv  = (const float*)d_in[2];
    const float* W_proj = (const float*)d_in[3];
    const float* b_proj = (const float*)d_in[4];
    const int*   amask  = (const int*)d_in[5];
    float* out = (float*)d_out;

    // 1. RoPE tables
    rope_table_kernel<<<SEQ, 32>>>();

    // 2. QKV GEMM + scatter to [b,h,l,d]
    {
        dim3 grid(QKV_N / 128, M_ROWS / 128);   // 24 x 64
        sgemm_kernel<<<grid, 256>>>(x, W_qkv, b_qkv, nullptr, QKV_N, DMODEL, 0);
    }

    // 3. RoPE on Q and K
    {
        int total = BATCH * NH * SEQ * 32;
        int blocks = (total + 255) / 256;
        rope_apply_kernel<<<blocks, 256>>>(0);
        rope_apply_kernel<<<blocks, 256>>>(1);
    }

    // 4. Flash attention
    {
        dim3 grid(SEQ / 128, BATCH * NH);       // 16 x 64
        flash_attn_kernel<<<grid, 128>>>(amask);
    }

    // 5. Output projection
    {
        dim3 grid(DMODEL / 128, M_ROWS / 128);  // 8 x 64
        sgemm_kernel<<<grid, 256>>>(nullptr, W_proj, b_proj, out, DMODEL, DMODEL, 1);
    }
}